// round 1
// baseline (speedup 1.0000x reference)
#include <cuda_runtime.h>
#include <cstdint>

typedef unsigned long long ull;

#define NNODES 20000
#define NEDGES 640000
#define IND    256
#define HID    128
#define NG     64

// XD GEMM split-K config
#define NB   136          // nodes per block
#define KBLK 148          // ceil(20000/136)
#define STG  8            // nodes staged per shared-memory round

// ---------------- device scratch (no allocations allowed) ----------------
__device__ int   g_C[NNODES * NG];          // [node][graph] counts, n-major
__device__ int   g_outdeg[NNODES];
__device__ int   g_cnt[NG];
__device__ float g_xdpart[KBLK][NG][IND];   // split-K partials (~9.7 MB)
__device__ float g_xspart[4][NG][IND];
__device__ float g_XF[2 * NG][IND];         // rows 0..63 = src-pool, 64..127 = dst-pool
__device__ float g_P[2][2 * NG][HID];       // layer activations

// ---------------- helpers ----------------
__device__ __forceinline__ ull pack2(float v) {
    ull r;
    asm("mov.b64 %0, {%1, %1};" : "=l"(r) : "r"(__float_as_uint(v)));
    return r;
}
__device__ __forceinline__ ull fma2(ull a, ull b, ull c) {
    ull d;
    asm("fma.rn.f32x2 %0, %1, %2, %3;" : "=l"(d) : "l"(a), "l"(b), "l"(c));
    return d;
}

// ---------------- kernels ----------------
__global__ void zero_k() {
    int i = blockIdx.x * blockDim.x + threadIdx.x;
    if (i < NNODES * NG) g_C[i] = 0;
    if (i < NNODES)      g_outdeg[i] = 0;
    if (i < NG)          g_cnt[i] = 0;
}

__global__ void count_k(const int* __restrict__ src, const int* __restrict__ dst,
                        const int* __restrict__ batch) {
    __shared__ int hist[NG];
    int t = threadIdx.x;
    if (t < NG) hist[t] = 0;
    __syncthreads();
    int e = blockIdx.x * blockDim.x + t;
    if (e < NEDGES) {
        int s = src[e];
        int d = dst[e];
        int g = batch[s];
        atomicAdd(&g_C[d * NG + g], 1);
        atomicAdd(&g_outdeg[s], 1);
        atomicAdd(&hist[g], 1);
    }
    __syncthreads();
    if (t < NG && hist[t]) atomicAdd(&g_cnt[t], hist[t]);
}

// src-side pool: per-graph segmented weighted sum (batch is sorted)
__global__ void xs_k(const float* __restrict__ x, const int* __restrict__ batch) {
    int g = blockIdx.x >> 2;
    int s = blockIdx.x & 3;
    __shared__ int sh[2];
    if (threadIdx.x < 2) {
        int target = g + threadIdx.x;
        int lo = 0, hi = NNODES;
        while (lo < hi) {
            int mid = (lo + hi) >> 1;
            if (batch[mid] < target) lo = mid + 1; else hi = mid;
        }
        sh[threadIdx.x] = lo;
    }
    __syncthreads();
    int st = sh[0], en = sh[1];
    int len = en - st;
    int a   = st + (len * s) / 4;
    int bnd = st + (len * (s + 1)) / 4;
    int tid = threadIdx.x;
    float acc = 0.0f;
    int n = a;
    for (; n + 4 <= bnd; n += 4) {
        float w0 = (float)g_outdeg[n + 0];
        float w1 = (float)g_outdeg[n + 1];
        float w2 = (float)g_outdeg[n + 2];
        float w3 = (float)g_outdeg[n + 3];
        float v0 = x[(n + 0) * IND + tid];
        float v1 = x[(n + 1) * IND + tid];
        float v2 = x[(n + 2) * IND + tid];
        float v3 = x[(n + 3) * IND + tid];
        acc += w0 * v0 + w1 * v1 + w2 * v2 + w3 * v3;
    }
    for (; n < bnd; n++) acc += (float)g_outdeg[n] * x[n * IND + tid];
    g_xspart[s][g][tid] = acc;
}

// dst-side pool: XD = C(64 x 20000) @ x(20000 x 256), split-K, fp32x2 packed FMA
__global__ void __launch_bounds__(256) xd_mm(const float* __restrict__ x) {
    __shared__ float xs[STG * IND];   // 8 KB
    __shared__ float cs[STG * NG];    // 2 KB
    int b   = blockIdx.x;
    int n0  = b * NB;
    int tid = threadIdx.x;
    int tm  = tid >> 5;    // 0..7   -> rows tm*8 .. tm*8+7
    int tn  = tid & 31;    // 0..31  -> cols tn*8 .. tn*8+7

    ull acc[8][4];
#pragma unroll
    for (int i = 0; i < 8; i++)
#pragma unroll
        for (int j = 0; j < 4; j++) acc[i][j] = 0ull;

    const float4* x4 = (const float4*)x;

    for (int s0 = 0; s0 < NB; s0 += STG) {
        // stage x: STG*IND floats = 512 float4, 2 per thread
        float4* xs4 = (float4*)xs;
#pragma unroll
        for (int v = 0; v < 2; v++) {
            int idx = tid + v * 256;        // [0,512)
            int ni  = idx >> 6;             // node in stage
            int c4  = idx & 63;             // float4 col
            int n   = n0 + s0 + ni;
            float4 val = make_float4(0.f, 0.f, 0.f, 0.f);
            if (n < NNODES) val = x4[n * (IND / 4) + c4];
            xs4[idx] = val;
        }
        // stage C: STG*NG ints = 512, 2 per thread (contiguous, n-major)
#pragma unroll
        for (int v = 0; v < 2; v++) {
            int idx = tid + v * 256;        // ni*64 + g
            int ni  = idx >> 6;
            int n   = n0 + s0 + ni;
            float val = 0.f;
            if (n < NNODES) val = (float)g_C[n * NG + (idx & 63)];
            cs[idx] = val;
        }
        __syncthreads();

#pragma unroll
        for (int kk = 0; kk < STG; kk++) {
            ulonglong2 p = *(ulonglong2*)&xs[kk * IND + tn * 8];
            ulonglong2 q = *(ulonglong2*)&xs[kk * IND + tn * 8 + 4];
            ull xv[4] = {p.x, p.y, q.x, q.y};
            float4 ca = *(float4*)&cs[kk * NG + tm * 8];
            float4 cb = *(float4*)&cs[kk * NG + tm * 8 + 4];
            float cv[8] = {ca.x, ca.y, ca.z, ca.w, cb.x, cb.y, cb.z, cb.w};
#pragma unroll
            for (int i = 0; i < 8; i++) {
                ull c2 = pack2(cv[i]);
#pragma unroll
                for (int j = 0; j < 4; j++) acc[i][j] = fma2(c2, xv[j], acc[i][j]);
            }
        }
        __syncthreads();
    }

    // write partials
#pragma unroll
    for (int i = 0; i < 8; i++) {
        int r = tm * 8 + i;
#pragma unroll
        for (int j = 0; j < 4; j++) {
            *(ull*)&g_xdpart[b][r][tn * 8 + j * 2] = acc[i][j];
        }
    }
}

// fold partials, normalize by counts (cnt==0 -> zero row)
__global__ void reduce_k() {
    int g = blockIdx.x;
    int c = threadIdx.x;
    int cnt = g_cnt[g];
    float inv = cnt > 0 ? 1.0f / (float)cnt : 0.0f;
    if (blockIdx.y == 0) {
        float acc = 0.f;
        for (int b = 0; b < KBLK; b++) acc += g_xdpart[b][g][c];
        g_XF[NG + g][c] = acc * inv;
    } else {
        float acc = 0.f;
#pragma unroll
        for (int s = 0; s < 4; s++) acc += g_xspart[s][g][c];
        g_XF[g][c] = acc * inv;
    }
}

// one affine layer: P = (A @ W + b) * flag ; scatter into output
__global__ void head_k(const float* __restrict__ A, int K,
                       const float* __restrict__ W, const float* __restrict__ bias,
                       float* __restrict__ Pout, float* __restrict__ out, int layer) {
    __shared__ float As[16][17];
    __shared__ float Ws[16][17];
    int r0 = blockIdx.y * 16;
    int c0 = blockIdx.x * 16;
    int ty = threadIdx.y, tx = threadIdx.x;
    float acc = 0.f;
    for (int k0 = 0; k0 < K; k0 += 16) {
        As[ty][tx] = A[(r0 + ty) * K + k0 + tx];
        Ws[ty][tx] = W[(k0 + ty) * HID + c0 + tx];
        __syncthreads();
#pragma unroll
        for (int kk = 0; kk < 16; kk++) acc += As[ty][kk] * Ws[kk][tx];
        __syncthreads();
    }
    int r = r0 + ty, c = c0 + tx;
    int g = r & (NG - 1);
    float flag = g_cnt[g] > 0 ? 1.0f : 0.0f;
    float v = (acc + bias[c]) * flag;
    if (Pout) Pout[r * HID + c] = v;
    int col = layer * 256 + ((r < NG) ? 0 : HID) + c;
    out[g * 768 + col] = v;
}

// ---------------- launcher ----------------
extern "C" void kernel_launch(void* const* d_in, const int* in_sizes, int n_in,
                              void* d_out, int out_size) {
    const float* x     = (const float*)d_in[0];
    const int*   eidx  = (const int*)d_in[1];
    const int*   batch = (const int*)d_in[2];
    const float* W0 = (const float*)d_in[3];
    const float* b0 = (const float*)d_in[4];
    const float* W1 = (const float*)d_in[5];
    const float* b1 = (const float*)d_in[6];
    const float* W2 = (const float*)d_in[7];
    const float* b2 = (const float*)d_in[8];
    float* out = (float*)d_out;

    const int* src = eidx;
    const int* dst = eidx + NEDGES;

    zero_k<<<(NNODES * NG + 255) / 256, 256>>>();
    count_k<<<(NEDGES + 255) / 256, 256>>>(src, dst, batch);
    xs_k<<<NG * 4, IND>>>(x, batch);
    xd_mm<<<KBLK, 256>>>(x);
    reduce_k<<<dim3(NG, 2), IND>>>();

    float *P0, *P1;
    cudaGetSymbolAddress((void**)&P0, g_P);
    P1 = P0 + 2 * NG * HID;
    float* XF;
    cudaGetSymbolAddress((void**)&XF, g_XF);

    dim3 hb(16, 16), hg(HID / 16, 2 * NG / 16);
    head_k<<<hg, hb>>>(XF, IND, W0, b0, P0, out, 0);
    head_k<<<hg, hb>>>(P0, HID, W1, b1, P1, out, 1);
    head_k<<<hg, hb>>>(P1, HID, W2, b2, nullptr, out, 2);
}

// round 2
// speedup vs baseline: 1.0881x; 1.0881x over previous
#include <cuda_runtime.h>
#include <cstdint>

typedef unsigned long long ull;

#define NNODES 20000
#define NEDGES 640000
#define IND    256
#define HID    128
#define NG     64

// XD GEMM split-K config: one CTA per SM, 512 threads, double-buffered
#define NB   136          // nodes per block
#define KBLK 148          // ceil(20000/136)
#define STG  8            // nodes staged per round
#define NSTAGE ((NB + STG - 1) / STG)   // 17

// ---------------- device scratch (no allocations allowed) ----------------
__device__ int   g_C[NNODES * NG];          // [node][graph] counts, n-major
__device__ int   g_outdeg[NNODES];
__device__ int   g_cnt[NG];
__device__ float g_xdpart[KBLK][NG][IND];   // split-K partials (~9.7 MB)
__device__ float g_xspart[4][NG][IND];
__device__ float g_XF[2 * NG][IND];         // rows 0..63 = src-pool, 64..127 = dst-pool
__device__ float g_P[2][2 * NG][HID];       // layer activations

// ---------------- helpers ----------------
__device__ __forceinline__ ull pack2(float v) {
    ull r;
    asm("mov.b64 %0, {%1, %1};" : "=l"(r) : "r"(__float_as_uint(v)));
    return r;
}
__device__ __forceinline__ ull fma2(ull a, ull b, ull c) {
    ull d;
    asm("fma.rn.f32x2 %0, %1, %2, %3;" : "=l"(d) : "l"(a), "l"(b), "l"(c));
    return d;
}

// ---------------- kernels ----------------
__global__ void zero_k() {
    int i = blockIdx.x * blockDim.x + threadIdx.x;
    if (i < NNODES * NG) g_C[i] = 0;
    if (i < NNODES)      g_outdeg[i] = 0;
    if (i < NG)          g_cnt[i] = 0;
}

__global__ void count_k(const int* __restrict__ src, const int* __restrict__ dst,
                        const int* __restrict__ batch) {
    __shared__ int hist[NG];
    int t = threadIdx.x;
    if (t < NG) hist[t] = 0;
    __syncthreads();
    int e = blockIdx.x * blockDim.x + t;
    if (e < NEDGES) {
        int s = src[e];
        int d = dst[e];
        int g = batch[s];
        atomicAdd(&g_C[d * NG + g], 1);
        atomicAdd(&g_outdeg[s], 1);
        atomicAdd(&hist[g], 1);
    }
    __syncthreads();
    if (t < NG && hist[t]) atomicAdd(&g_cnt[t], hist[t]);
}

// src-side pool: per-graph segmented weighted sum (batch is sorted)
__global__ void xs_k(const float* __restrict__ x, const int* __restrict__ batch) {
    int g = blockIdx.x >> 2;
    int s = blockIdx.x & 3;
    __shared__ int sh[2];
    if (threadIdx.x < 2) {
        int target = g + threadIdx.x;
        int lo = 0, hi = NNODES;
        while (lo < hi) {
            int mid = (lo + hi) >> 1;
            if (batch[mid] < target) lo = mid + 1; else hi = mid;
        }
        sh[threadIdx.x] = lo;
    }
    __syncthreads();
    int st = sh[0], en = sh[1];
    int len = en - st;
    int a   = st + (len * s) / 4;
    int bnd = st + (len * (s + 1)) / 4;
    int tid = threadIdx.x;
    float acc = 0.0f;
    int n = a;
    for (; n + 4 <= bnd; n += 4) {
        float w0 = (float)g_outdeg[n + 0];
        float w1 = (float)g_outdeg[n + 1];
        float w2 = (float)g_outdeg[n + 2];
        float w3 = (float)g_outdeg[n + 3];
        float v0 = x[(n + 0) * IND + tid];
        float v1 = x[(n + 1) * IND + tid];
        float v2 = x[(n + 2) * IND + tid];
        float v3 = x[(n + 3) * IND + tid];
        acc += w0 * v0 + w1 * v1 + w2 * v2 + w3 * v3;
    }
    for (; n < bnd; n++) acc += (float)g_outdeg[n] * x[n * IND + tid];
    g_xspart[s][g][tid] = acc;
}

// dst-side pool: XD = C(64 x 20000) @ x(20000 x 256), split-K, fp32x2 packed FMA.
// 512 threads, 4x8 tile/thread, double-buffered smem, 1 barrier/stage,
// conflict-free LDS.128 (cols {tn*4..+3} and {128+tn*4..+3}).
__global__ void __launch_bounds__(512, 1) xd_mm(const float* __restrict__ x) {
    __shared__ float xs[2][STG * IND];   // 2 x 8 KB
    __shared__ float cs[2][STG * NG];    // 2 x 2 KB
    int b   = blockIdx.x;
    int n0  = b * NB;
    int tid = threadIdx.x;
    int tm  = tid >> 5;    // warp id 0..15 -> rows tm*4 .. tm*4+3
    int tn  = tid & 31;    // lane -> cols tn*4..+3 and 128+tn*4..+3

    // staging decomposition: 512 threads cover STG*64 float4 of x and STG*64 counts
    int ni = tid >> 6;     // node-in-stage 0..7
    int cg = tid & 63;     // float4-col for x / graph for C

    ull acc[4][4];
#pragma unroll
    for (int i = 0; i < 4; i++)
#pragma unroll
        for (int j = 0; j < 4; j++) acc[i][j] = 0ull;

    const float4* x4 = (const float4*)x;

    // prefetch stage 0
    float4 xr; float cr;
    {
        int n = n0 + ni;
        bool ok = n < NNODES;
        xr = ok ? x4[n * (IND / 4) + cg] : make_float4(0.f, 0.f, 0.f, 0.f);
        cr = ok ? (float)g_C[n * NG + cg] : 0.f;
    }
    ((float4*)xs[0])[tid] = xr;
    cs[0][tid] = cr;

    for (int s = 0; s < NSTAGE; s++) {
        __syncthreads();
        int buf = s & 1;
        // prefetch next stage (global loads issued early, consumed after compute)
        float4 xr_n; float cr_n;
        if (s + 1 < NSTAGE) {
            int n = n0 + (s + 1) * STG + ni;
            bool ok = n < NNODES;
            xr_n = ok ? x4[n * (IND / 4) + cg] : make_float4(0.f, 0.f, 0.f, 0.f);
            cr_n = ok ? (float)g_C[n * NG + cg] : 0.f;
        }
        // compute on current buffer
#pragma unroll
        for (int kk = 0; kk < STG; kk++) {
            ulonglong2 p = *(ulonglong2*)&xs[buf][kk * IND + tn * 4];        // cols tn*4..+3
            ulonglong2 q = *(ulonglong2*)&xs[buf][kk * IND + 128 + tn * 4];  // cols 128+tn*4..+3
            ull xv[4] = {p.x, p.y, q.x, q.y};
            float4 ca = *(float4*)&cs[buf][kk * NG + tm * 4];                // broadcast in warp
            float cv[4] = {ca.x, ca.y, ca.z, ca.w};
#pragma unroll
            for (int i = 0; i < 4; i++) {
                ull c2 = pack2(cv[i]);
#pragma unroll
                for (int j = 0; j < 4; j++) acc[i][j] = fma2(c2, xv[j], acc[i][j]);
            }
        }
        // store next stage into the other buffer (safe: buf^1 readers finished
        // before the barrier at the top of this iteration)
        if (s + 1 < NSTAGE) {
            ((float4*)xs[buf ^ 1])[tid] = xr_n;
            cs[buf ^ 1][tid] = cr_n;
        }
    }

    // write partials: row r, 16B per chunk, warp-contiguous
#pragma unroll
    for (int i = 0; i < 4; i++) {
        int r = tm * 4 + i;
        ulonglong2 lo; lo.x = acc[i][0]; lo.y = acc[i][1];
        ulonglong2 hi; hi.x = acc[i][2]; hi.y = acc[i][3];
        *(ulonglong2*)&g_xdpart[b][r][tn * 4]       = lo;
        *(ulonglong2*)&g_xdpart[b][r][128 + tn * 4] = hi;
    }
}

// fold partials, normalize by counts (cnt==0 -> zero row)
__global__ void reduce_k() {
    int g = blockIdx.x;
    int c = threadIdx.x;
    int cnt = g_cnt[g];
    float inv = cnt > 0 ? 1.0f / (float)cnt : 0.0f;
    if (blockIdx.y == 0) {
        float a0 = 0.f, a1 = 0.f, a2 = 0.f, a3 = 0.f;
        int bq;
        for (bq = 0; bq + 4 <= KBLK; bq += 4) {
            a0 += g_xdpart[bq + 0][g][c];
            a1 += g_xdpart[bq + 1][g][c];
            a2 += g_xdpart[bq + 2][g][c];
            a3 += g_xdpart[bq + 3][g][c];
        }
        float acc = (a0 + a1) + (a2 + a3);
        for (; bq < KBLK; bq++) acc += g_xdpart[bq][g][c];
        g_XF[NG + g][c] = acc * inv;
    } else {
        float acc = 0.f;
#pragma unroll
        for (int s = 0; s < 4; s++) acc += g_xspart[s][g][c];
        g_XF[g][c] = acc * inv;
    }
}

// one affine layer: P = (A @ W + b) * flag ; scatter into output
__global__ void head_k(const float* __restrict__ A, int K,
                       const float* __restrict__ W, const float* __restrict__ bias,
                       float* __restrict__ Pout, float* __restrict__ out, int layer) {
    __shared__ float As[16][17];
    __shared__ float Ws[16][17];
    int r0 = blockIdx.y * 16;
    int c0 = blockIdx.x * 16;
    int ty = threadIdx.y, tx = threadIdx.x;
    float acc = 0.f;
    for (int k0 = 0; k0 < K; k0 += 16) {
        As[ty][tx] = A[(r0 + ty) * K + k0 + tx];
        Ws[ty][tx] = W[(k0 + ty) * HID + c0 + tx];
        __syncthreads();
#pragma unroll
        for (int kk = 0; kk < 16; kk++) acc += As[ty][kk] * Ws[kk][tx];
        __syncthreads();
    }
    int r = r0 + ty, c = c0 + tx;
    int g = r & (NG - 1);
    float flag = g_cnt[g] > 0 ? 1.0f : 0.0f;
    float v = (acc + bias[c]) * flag;
    if (Pout) Pout[r * HID + c] = v;
    int col = layer * 256 + ((r < NG) ? 0 : HID) + c;
    out[g * 768 + col] = v;
}

// ---------------- launcher ----------------
extern "C" void kernel_launch(void* const* d_in, const int* in_sizes, int n_in,
                              void* d_out, int out_size) {
    const float* x     = (const float*)d_in[0];
    const int*   eidx  = (const int*)d_in[1];
    const int*   batch = (const int*)d_in[2];
    const float* W0 = (const float*)d_in[3];
    const float* b0 = (const float*)d_in[4];
    const float* W1 = (const float*)d_in[5];
    const float* b1 = (const float*)d_in[6];
    const float* W2 = (const float*)d_in[7];
    const float* b2 = (const float*)d_in[8];
    float* out = (float*)d_out;

    const int* src = eidx;
    const int* dst = eidx + NEDGES;

    zero_k<<<(NNODES * NG + 255) / 256, 256>>>();
    count_k<<<(NEDGES + 255) / 256, 256>>>(src, dst, batch);
    xs_k<<<NG * 4, IND>>>(x, batch);
    xd_mm<<<KBLK, 512>>>(x);
    reduce_k<<<dim3(NG, 2), IND>>>();

    float *P0, *P1;
    cudaGetSymbolAddress((void**)&P0, g_P);
    P1 = P0 + 2 * NG * HID;
    float* XF;
    cudaGetSymbolAddress((void**)&XF, g_XF);

    dim3 hb(16, 16), hg(HID / 16, 2 * NG / 16);
    head_k<<<hg, hb>>>(XF, IND, W0, b0, P0, out, 0);
    head_k<<<hg, hb>>>(P0, HID, W1, b1, P1, out, 1);
    head_k<<<hg, hb>>>(P1, HID, W2, b2, nullptr, out, 2);
}